// round 3
// baseline (speedup 1.0000x reference)
#include <cuda_runtime.h>
#include <cstdint>

// out = X * W[idx][0] + Y * W[idx][1], idx = reward[b,s] in {0,1}
// Shapes: X,Y: (4, 4096, 2048) fp32; reward: (4,4096,1) int (JAX downcasts
// int64 -> int32 without x64 mode); W: (2,2) fp32.
// Pure HBM-bound elementwise blend. float4 vectorization, flat grid.

__global__ __launch_bounds__(256)
void blend_kernel(const float4* __restrict__ X,
                  const float4* __restrict__ Y,
                  const int* __restrict__ reward,
                  const float* __restrict__ W,
                  float4* __restrict__ out,
                  int n4)
{
    int i = blockIdx.x * blockDim.x + threadIdx.x;
    if (i >= n4) return;

    // D = 2048 floats = 512 float4 per (b,s) row
    int row = i >> 9;
    int idx = reward[row];
    // Harden: idx must be 0/1. If dtype assumption is wrong this turns a
    // device fault into a visible rel_err instead.
    idx = (idx != 0) ? 1 : 0;

    float a = W[2 * idx];
    float b = W[2 * idx + 1];

    float4 x = X[i];
    float4 y = Y[i];

    float4 o;
    o.x = fmaf(x.x, a, y.x * b);
    o.y = fmaf(x.y, a, y.y * b);
    o.z = fmaf(x.z, a, y.z * b);
    o.w = fmaf(x.w, a, y.w * b);

    out[i] = o;
}

extern "C" void kernel_launch(void* const* d_in, const int* in_sizes, int n_in,
                              void* d_out, int out_size)
{
    const float4* X      = (const float4*)d_in[0];
    const float4* Y      = (const float4*)d_in[1];
    const int*    reward = (const int*)d_in[2];
    const float*  W      = (const float*)d_in[3];
    float4*       out    = (float4*)d_out;

    int n  = out_size;          // total fp32 elements = 4*4096*2048
    int n4 = n / 4;             // float4 count

    int threads = 256;
    int blocks  = (n4 + threads - 1) / threads;
    blend_kernel<<<blocks, threads>>>(X, Y, reward, W, out, n4);
}

// round 4
// speedup vs baseline: 1.0661x; 1.0661x over previous
#include <cuda_runtime.h>
#include <cstdint>

// out = X * W[idx][0] + Y * W[idx][1], idx = reward[b,s] in {0,1}
// X,Y: (4,4096,2048) fp32; reward: (4,4096,1) int32; W: (2,2) fp32.
// HBM-bound blend. 2x float4 per thread, loads front-batched for MLP.

__global__ __launch_bounds__(256)
void blend_kernel2(const float4* __restrict__ X,
                   const float4* __restrict__ Y,
                   const int* __restrict__ reward,
                   const float* __restrict__ W,
                   float4* __restrict__ out,
                   int n4)
{
    // Each thread handles two consecutive float4: indices i and i+1.
    int t = blockIdx.x * blockDim.x + threadIdx.x;
    int i = t * 2;
    if (i >= n4) return;

    // 512 float4 per (b,s) row; pair (i, i+1) is always inside one row.
    int row = i >> 9;
    int idx = reward[row];
    idx = (idx != 0) ? 1 : 0;

    // Front-batch all global loads (maximize outstanding loads).
    float4 x0 = X[i];
    float4 y0 = Y[i];
    float4 x1 = X[i + 1];
    float4 y1 = Y[i + 1];

    float a = W[2 * idx];
    float b = W[2 * idx + 1];

    float4 o0, o1;
    o0.x = fmaf(x0.x, a, y0.x * b);
    o0.y = fmaf(x0.y, a, y0.y * b);
    o0.z = fmaf(x0.z, a, y0.z * b);
    o0.w = fmaf(x0.w, a, y0.w * b);
    o1.x = fmaf(x1.x, a, y1.x * b);
    o1.y = fmaf(x1.y, a, y1.y * b);
    o1.z = fmaf(x1.z, a, y1.z * b);
    o1.w = fmaf(x1.w, a, y1.w * b);

    out[i]     = o0;
    out[i + 1] = o1;
}

extern "C" void kernel_launch(void* const* d_in, const int* in_sizes, int n_in,
                              void* d_out, int out_size)
{
    const float4* X      = (const float4*)d_in[0];
    const float4* Y      = (const float4*)d_in[1];
    const int*    reward = (const int*)d_in[2];
    const float*  W      = (const float*)d_in[3];
    float4*       out    = (float4*)d_out;

    int n  = out_size;      // 4*4096*2048 fp32
    int n4 = n / 4;         // float4 count (even, rows of 512)

    int threads = 256;
    int per_block = threads * 2;
    int blocks = (n4 + per_block - 1) / per_block;
    blend_kernel2<<<blocks, threads>>>(X, Y, reward, W, out, n4);
}